// round 8
// baseline (speedup 1.0000x reference)
#include <cuda_runtime.h>
#include <stdint.h>

// SpikeFP64Divider: gate-level FP64 restoring divider on rows of 64 {0,1} floats.
// Integer replica of the exact circuit semantics (13-bit modular exponent math,
// subnormal inputs treated as normals, mantissa-round carry-out structurally 0).
//
// R8 = R7 (16 rows/warp, LDG.128/STG.128, ballot transpose) with the assembly
// fix: fetch capA and capB with separate shuffles (ownership spans both warp
// halves, so a single half-selected `offer` register fetched wrong data).

static __device__ __forceinline__ uint64_t spread4(uint32_t h16) {
    // 16-bit input, bit m -> bit 4m of a 64-bit word
    uint64_t x = h16;
    x = (x | (x << 24)) & 0x000000FF000000FFull;
    x = (x | (x << 12)) & 0x000F000F000F000Full;
    x = (x | (x << 6))  & 0x0303030303030303ull;
    x = (x | (x << 3))  & 0x1111111111111111ull;
    return x;
}

__global__ __launch_bounds__(256, 5) void spike_div_kernel(
    const float* __restrict__ A, const float* __restrict__ B, float* __restrict__ O)
{
    const unsigned FULL = 0xFFFFFFFFu;
    const int lane = threadIdx.x & 31;
    const int warp = threadIdx.x >> 5;

    // Each warp owns 16 consecutive rows = 1024 floats = 256 uint4.
    // uint4 index i = k*32 + lane -> row 2k + (lane>>4), cols 4*(lane&15)..+3
    const long long elemBase = (((long long)blockIdx.x * 8 + warp) * 16) * 64;
    const uint4* __restrict__ Au = reinterpret_cast<const uint4*>(A + elemBase);
    const uint4* __restrict__ Bu = reinterpret_cast<const uint4*>(B + elemBase);

    // ---- Pack: ballot per vector component; ballot (load k, comp j) covers
    // row 2k (low 16 bits) and row 2k+1 (high 16 bits), cols 4m+j.
    // Owner: A-ballot (k,j) -> lane 4k+j ; B-ballot (k,j) -> lane (4k+j)^16.
    uint32_t capA = 0u, capB = 0u;
#pragma unroll
    for (int k0 = 0; k0 < 8; k0 += 2) {
        uint4 xa0 = Au[(k0 + 0) * 32 + lane];
        uint4 xa1 = Au[(k0 + 1) * 32 + lane];
        uint4 xb0 = Bu[(k0 + 0) * 32 + lane];
        uint4 xb1 = Bu[(k0 + 1) * 32 + lane];
#pragma unroll
        for (int jj = 0; jj < 8; jj++) {
            const int k = k0 + (jj >> 2);
            const int j = jj & 3;
            const uint4& va = (jj < 4) ? xa0 : xa1;
            const uint4& vb = (jj < 4) ? xb0 : xb1;
            const uint32_t ca = (j == 0) ? va.x : (j == 1) ? va.y : (j == 2) ? va.z : va.w;
            const uint32_t cb = (j == 0) ? vb.x : (j == 1) ? vb.y : (j == 2) ? vb.z : vb.w;
            const uint32_t ba = __ballot_sync(FULL, ca != 0u);
            if (lane == (4 * k + j))         capA = ba;
            const uint32_t bb = __ballot_sync(FULL, cb != 0u);
            if (lane == ((4 * k + j) ^ 16))  capB = bb;
        }
    }

    // ---- Assemble: lane l<16 builds A-word of row l; lane l>=16 builds
    // B-word of row l-16. Ballot bit m (in my half) = col 4m+j:
    // spread4 -> bit 4m, brev64 -> 63-4m, >>j -> 63-(4m+j).
    // Both capA and capB shuffles are issued; requester half selects.
    const int row = lane & 15;
    uint64_t w_mine = 0ull;
#pragma unroll
    for (int j = 0; j < 4; j++) {
        const int srcA = 4 * (row >> 1) + j;       // lane holding A-ballot (k,j)
        const uint32_t balA = __shfl_sync(FULL, capA, srcA);
        const uint32_t balB = __shfl_sync(FULL, capB, srcA ^ 16);
        const uint32_t bal = (lane < 16) ? balA : balB;
        const uint32_t h = (row & 1) ? (bal >> 16) : (bal & 0xFFFFu);
        w_mine |= (__brevll(spread4(h)) >> j);
    }
    const uint64_t wa = w_mine;                                  // valid on lanes 0-15
    const uint64_t wb = __shfl_sync(FULL, w_mine, lane ^ 16);    // B-word for my row

    // ---- Circuit replica (row `lane` on lanes 0-15; junk on high lanes) ----
    const uint64_t M52 = 0x000FFFFFFFFFFFFFull;
    const uint32_t s_out = (uint32_t)((wa ^ wb) >> 63);
    const uint32_t ea = (uint32_t)(wa >> 52) & 0x7FFu;
    const uint32_t eb = (uint32_t)(wb >> 52) & 0x7FFu;
    const uint64_t ma = wa & M52;
    const uint64_t mb = wb & M52;

    const bool a_zero = (ea == 0u)     && (ma == 0ull);
    const bool b_zero = (eb == 0u)     && (mb == 0ull);
    const bool a_inf  = (ea == 0x7FFu) && (ma == 0ull);
    const bool b_inf  = (eb == 0x7FFu) && (mb == 0ull);
    const bool a_nan  = (ea == 0x7FFu) && (ma != 0ull);
    const bool b_nan  = (eb == 0x7FFu) && (mb != 0ull);

    const bool r_nan  = a_nan || b_nan || (a_zero && b_zero) || (a_inf && b_inf);
    const bool r_inf  = (!a_zero && b_zero) || (a_inf && !b_inf);
    const bool r_zero = (a_zero && !b_zero) || (!a_inf && b_inf);

    // 13-bit modular exponent arithmetic, as the ripple circuits do.
    int exp13 = ((int)ea - (int)eb + 1023) & 8191;

    // ---- Exact Q = floor(a * 2^56 / d) via 2 base-2^28 digits ----
    const uint64_t a = (1ull << 53) | (ma << 1);
    const uint64_t d = (1ull << 53) | (mb << 1);
    const int64_t  ds = (int64_t)d;
    const double inv = 1.0 / (double)d;

    int64_t q1 = (int64_t)((double)a * 0x1p28 * inv);
    int64_t r1 = (int64_t)((a << 28) - (uint64_t)q1 * d);
    if (r1 < 0)   { q1--; r1 += ds; }
    if (r1 < 0)   { q1--; r1 += ds; }
    if (r1 >= ds) { q1++; r1 -= ds; }

    int64_t q2 = (int64_t)((double)r1 * 0x1p28 * inv);
    int64_t r2 = (int64_t)(((uint64_t)r1 << 28) - (uint64_t)q2 * d);
    if (r2 < 0)   { q2--; r2 += ds; }
    if (r2 < 0)   { q2--; r2 += ds; }
    if (r2 >= ds) { q2++; r2 -= ds; }

    const uint64_t Q = ((uint64_t)q1 << 28) + (uint64_t)q2;  // 57-bit quotient
    const bool remnz = (r2 != 0);

    // Normalize + guard/round/sticky (Q bit 56 = first quotient bit).
    const uint32_t q0 = (uint32_t)(Q >> 56) & 1u;
    uint64_t mant;
    uint32_t rnd;
    bool sticky;
    if (q0) {
        mant   = (Q >> 4) & M52;
        rnd    = (uint32_t)(Q >> 3) & 1u;
        sticky = ((Q & 7ull) != 0ull) || remnz;
    } else {
        mant   = (Q >> 3) & M52;
        rnd    = (uint32_t)(Q >> 2) & 1u;
        sticky = ((Q & 3ull) != 0ull) || remnz;
        exp13  = (exp13 - 1) & 8191;
    }

    // RNE; circuit's 53-bit incrementer carry-out is structurally 0:
    // mantissa overflow wraps to 0 WITHOUT exponent bump (mask only).
    const uint32_t lsb = (uint32_t)mant & 1u;
    const uint32_t rup = (rnd && (sticky || lsb)) ? 1u : 0u;
    mant = (mant + (uint64_t)rup) & M52;

    const uint32_t exp_field = (uint32_t)exp13 & 0x7FFu;
    const bool ovf = ((exp13 >> 11) & 3) != 0;
    const bool unf = (((exp13 >> 12) & 1) != 0) || (exp13 == 0);

    const uint64_t sbit = (uint64_t)s_out << 63;
    uint64_t out;
    if (r_nan)       out = sbit | (0x7FFull << 52) | (1ull << 51);
    else if (r_inf)  out = sbit | (0x7FFull << 52);
    else if (r_zero) out = sbit;
    else if (ovf)    out = sbit | (0x7FFull << 52);
    else if (unf)    out = sbit;
    else             out = sbit | ((uint64_t)exp_field << 52) | mant;

    // ---- Unpack: shuffle hi/lo from owner lane (rows on lanes 0-15),
    // STG.128 float4. float4 i = k*32+lane: row 2k+(lane>>4), nib lane&15.
    const uint32_t hi_o = (uint32_t)(out >> 32);   // cols  0..31 (col c at bit 31-c)
    const uint32_t lo_o = (uint32_t)out;           // cols 32..63
    float4* __restrict__ O4 = reinterpret_cast<float4*>(O + elemBase);
    const int hsel = (lane >> 4) & 1;              // which row of the pair I store
    const bool use_lo = (lane & 8) != 0;           // my 4 cols live in lo word?
    const int nsh = 28 - 4 * (lane & 7);           // nibble shift within word
#pragma unroll
    for (int k = 0; k < 8; k++) {
        const int src = 2 * k + hsel;              // row index = owner lane
        const uint32_t wh = __shfl_sync(FULL, hi_o, src);
        const uint32_t wl = __shfl_sync(FULL, lo_o, src);
        const uint32_t word = use_lo ? wl : wh;
        const uint32_t nib = (word >> nsh) & 0xFu;
        float4 v;
        v.x = __uint_as_float((nib & 8u) ? 0x3F800000u : 0u);
        v.y = __uint_as_float((nib & 4u) ? 0x3F800000u : 0u);
        v.z = __uint_as_float((nib & 2u) ? 0x3F800000u : 0u);
        v.w = __uint_as_float((nib & 1u) ? 0x3F800000u : 0u);
        O4[k * 32 + lane] = v;
    }
}

extern "C" void kernel_launch(void* const* d_in, const int* in_sizes, int n_in,
                              void* d_out, int out_size) {
    const float* A = (const float*)d_in[0];
    const float* B = (const float*)d_in[1];
    float* O = (float*)d_out;
    const int rows = in_sizes[0] / 64;       // 131072
    const int grid = rows / 128;             // 1024 blocks, 8 warps x 16 rows
    spike_div_kernel<<<grid, 256>>>(A, B, O);
}

// round 9
// speedup vs baseline: 1.1943x; 1.1943x over previous
#include <cuda_runtime.h>
#include <stdint.h>

// SpikeFP64Divider: gate-level FP64 restoring divider on rows of 64 {0,1} floats.
// Integer replica of the exact circuit semantics (13-bit modular exponent math,
// subnormal inputs treated as normals, mantissa-round carry-out structurally 0).
//
// R9: cp.async staging. All global loads issued as fire-and-forget 16B async
// copies into swizzled smem (MLP decoupled from registers/ballots), then each
// lane packs its own row from smem (no ballots, no captures, 32 rows/warp,
// all lanes productive). Unpack/store = R5's verified shuffle + STG.128 path.

static __device__ __forceinline__ void cp_async16(uint32_t dst, const void* src) {
    asm volatile("cp.async.cg.shared.global [%0], [%1], 16;" :: "r"(dst), "l"(src));
}

__global__ __launch_bounds__(64) void spike_div_kernel(
    const float* __restrict__ A, const float* __restrict__ B, float* __restrict__ O)
{
    // [warp][array][row][chunk] ; chunk swizzled by (row & 7). 32 KB total.
    __shared__ uint4 buf[2][2][32][16];

    const unsigned FULL = 0xFFFFFFFFu;
    const int lane = threadIdx.x & 31;
    const int warp = threadIdx.x >> 5;

    // Each warp owns 32 consecutive rows = 2048 floats = 512 uint4 chunks.
    const long long rowBase = ((long long)blockIdx.x * 2 + warp) * 32;
    const uint4* __restrict__ Ag = reinterpret_cast<const uint4*>(A) + rowBase * 16;
    const uint4* __restrict__ Bg = reinterpret_cast<const uint4*>(B) + rowBase * 16;

    // ---- Load phase: 32 cp.async per lane, no register staging, no stalls ----
    // chunk g = i*32 + lane -> row r = g>>4, chunk k = g&15 ; dst chunk k^(r&7).
#pragma unroll
    for (int i = 0; i < 16; i++) {
        const int g = i * 32 + lane;
        const int r = g >> 4;
        const int k = (g & 15) ^ (r & 7);
        cp_async16((uint32_t)__cvta_generic_to_shared(&buf[warp][0][r][k]), Ag + g);
    }
#pragma unroll
    for (int i = 0; i < 16; i++) {
        const int g = i * 32 + lane;
        const int r = g >> 4;
        const int k = (g & 15) ^ (r & 7);
        cp_async16((uint32_t)__cvta_generic_to_shared(&buf[warp][1][r][k]), Bg + g);
    }
    asm volatile("cp.async.commit_group;");
    asm volatile("cp.async.wait_group 0;" ::: "memory");
    __syncthreads();

    // ---- Pack: lane l packs row l of A and B straight from smem ----
    // Chunk k holds cols 4k..4k+3 ; col c -> bit 63-c ; component !=0 test is
    // bit 29 of the float encoding (1.0f = 0x3F800000).
    uint32_t hiA = 0u, loA = 0u, hiB = 0u, loB = 0u;
#pragma unroll
    for (int k = 0; k < 16; k++) {
        const int ks = k ^ (lane & 7);             // conflict-free per 8-lane phase
        const uint4 va = buf[warp][0][lane][ks];
        const uint32_t na = ((va.x >> 26) & 8u) | ((va.y >> 27) & 4u) |
                            ((va.z >> 28) & 2u) | ((va.w >> 29) & 1u);
        const uint4 vb = buf[warp][1][lane][ks];
        const uint32_t nb = ((vb.x >> 26) & 8u) | ((vb.y >> 27) & 4u) |
                            ((vb.z >> 28) & 2u) | ((vb.w >> 29) & 1u);
        if (k < 8) { hiA |= na << (28 - 4 * k);       hiB |= nb << (28 - 4 * k); }
        else       { loA |= na << (28 - 4 * (k - 8)); loB |= nb << (28 - 4 * (k - 8)); }
    }
    const uint64_t wa = ((uint64_t)hiA << 32) | (uint64_t)loA;
    const uint64_t wb = ((uint64_t)hiB << 32) | (uint64_t)loB;

    // ---- Circuit replica (one row per lane, all 32 lanes productive) ----
    const uint64_t M52 = 0x000FFFFFFFFFFFFFull;
    const uint32_t s_out = (uint32_t)((wa ^ wb) >> 63);
    const uint32_t ea = (uint32_t)(wa >> 52) & 0x7FFu;
    const uint32_t eb = (uint32_t)(wb >> 52) & 0x7FFu;
    const uint64_t ma = wa & M52;
    const uint64_t mb = wb & M52;

    const bool a_zero = (ea == 0u)     && (ma == 0ull);
    const bool b_zero = (eb == 0u)     && (mb == 0ull);
    const bool a_inf  = (ea == 0x7FFu) && (ma == 0ull);
    const bool b_inf  = (eb == 0x7FFu) && (mb == 0ull);
    const bool a_nan  = (ea == 0x7FFu) && (ma != 0ull);
    const bool b_nan  = (eb == 0x7FFu) && (mb != 0ull);

    const bool r_nan  = a_nan || b_nan || (a_zero && b_zero) || (a_inf && b_inf);
    const bool r_inf  = (!a_zero && b_zero) || (a_inf && !b_inf);
    const bool r_zero = (a_zero && !b_zero) || (!a_inf && b_inf);

    // 13-bit modular exponent arithmetic, as the ripple circuits do.
    int exp13 = ((int)ea - (int)eb + 1023) & 8191;

    // ---- Exact Q = floor(a * 2^56 / d) via 2 base-2^28 digits ----
    const uint64_t a = (1ull << 53) | (ma << 1);
    const uint64_t d = (1ull << 53) | (mb << 1);
    const int64_t  ds = (int64_t)d;
    const double inv = 1.0 / (double)d;

    int64_t q1 = (int64_t)((double)a * 0x1p28 * inv);
    int64_t r1 = (int64_t)((a << 28) - (uint64_t)q1 * d);
    if (r1 < 0)   { q1--; r1 += ds; }
    if (r1 < 0)   { q1--; r1 += ds; }
    if (r1 >= ds) { q1++; r1 -= ds; }

    int64_t q2 = (int64_t)((double)r1 * 0x1p28 * inv);
    int64_t r2 = (int64_t)(((uint64_t)r1 << 28) - (uint64_t)q2 * d);
    if (r2 < 0)   { q2--; r2 += ds; }
    if (r2 < 0)   { q2--; r2 += ds; }
    if (r2 >= ds) { q2++; r2 -= ds; }

    const uint64_t Q = ((uint64_t)q1 << 28) + (uint64_t)q2;  // 57-bit quotient
    const bool remnz = (r2 != 0);

    // Normalize + guard/round/sticky (Q bit 56 = first quotient bit).
    const uint32_t q0 = (uint32_t)(Q >> 56) & 1u;
    uint64_t mant;
    uint32_t rnd;
    bool sticky;
    if (q0) {
        mant   = (Q >> 4) & M52;
        rnd    = (uint32_t)(Q >> 3) & 1u;
        sticky = ((Q & 7ull) != 0ull) || remnz;
    } else {
        mant   = (Q >> 3) & M52;
        rnd    = (uint32_t)(Q >> 2) & 1u;
        sticky = ((Q & 3ull) != 0ull) || remnz;
        exp13  = (exp13 - 1) & 8191;
    }

    // RNE; circuit's 53-bit incrementer carry-out is structurally 0:
    // mantissa overflow wraps to 0 WITHOUT exponent bump (mask only).
    const uint32_t lsb = (uint32_t)mant & 1u;
    const uint32_t rup = (rnd && (sticky || lsb)) ? 1u : 0u;
    mant = (mant + (uint64_t)rup) & M52;

    const uint32_t exp_field = (uint32_t)exp13 & 0x7FFu;
    const bool ovf = ((exp13 >> 11) & 3) != 0;
    const bool unf = (((exp13 >> 12) & 1) != 0) || (exp13 == 0);

    const uint64_t sbit = (uint64_t)s_out << 63;
    uint64_t out;
    if (r_nan)       out = sbit | (0x7FFull << 52) | (1ull << 51);
    else if (r_inf)  out = sbit | (0x7FFull << 52);
    else if (r_zero) out = sbit;
    else if (ovf)    out = sbit | (0x7FFull << 52);
    else if (unf)    out = sbit;
    else             out = sbit | ((uint64_t)exp_field << 52) | mant;

    // ---- Unpack: shuffle hi/lo from owner lane (lane r owns row r),
    // STG.128 float4. float4 i = k*32+lane: row 2k+(lane>>4), nib lane&15.
    const uint32_t hi_o = (uint32_t)(out >> 32);   // cols  0..31 (col c at bit 31-c)
    const uint32_t lo_o = (uint32_t)out;           // cols 32..63
    float4* __restrict__ O4 = reinterpret_cast<float4*>(O + rowBase * 64);
    const int hsel = (lane >> 4) & 1;              // which row of the pair I store
    const bool use_lo = (lane & 8) != 0;           // my 4 cols live in lo word?
    const int nsh = 28 - 4 * (lane & 7);           // nibble shift within word
#pragma unroll
    for (int k = 0; k < 16; k++) {
        const int src = 2 * k + hsel;              // row index = owner lane
        const uint32_t wh = __shfl_sync(FULL, hi_o, src);
        const uint32_t wl = __shfl_sync(FULL, lo_o, src);
        const uint32_t word = use_lo ? wl : wh;
        const uint32_t nib = (word >> nsh) & 0xFu;
        float4 v;
        v.x = __uint_as_float((nib & 8u) ? 0x3F800000u : 0u);
        v.y = __uint_as_float((nib & 4u) ? 0x3F800000u : 0u);
        v.z = __uint_as_float((nib & 2u) ? 0x3F800000u : 0u);
        v.w = __uint_as_float((nib & 1u) ? 0x3F800000u : 0u);
        O4[k * 32 + lane] = v;
    }
}

extern "C" void kernel_launch(void* const* d_in, const int* in_sizes, int n_in,
                              void* d_out, int out_size) {
    const float* A = (const float*)d_in[0];
    const float* B = (const float*)d_in[1];
    float* O = (float*)d_out;
    const int rows = in_sizes[0] / 64;       // 131072
    const int grid = rows / 64;              // 2048 blocks, 2 warps x 32 rows
    spike_div_kernel<<<grid, 64>>>(A, B, O);
}